// round 9
// baseline (speedup 1.0000x reference)
#include <cuda_runtime.h>
#include <math.h>

#define E_    4
#define C_    64
#define HID_  128
#define B_    16
#define HW_   16384      // 128*128
#define TP    128        // pixels per tile
#define NT    512        // threads per block (main kernel)
#define BN_EPS_ 1e-5f

// ---------------- device scratch (no allocs allowed) ----------------
__device__ float g_W1T[E_*C_*HID_];     // [e][c][o]   (BN scale folded)
__device__ float g_t1 [E_*HID_];        // fused bias layer1
__device__ float g_W2T[E_*HID_*HID_];   // [e][i][o]   (BN scale folded)
__device__ float g_t2 [E_*HID_];
__device__ float g_W3T[E_*HID_*C_];     // [e][i][ch]
__device__ float g_gap[B_*C_];
__device__ int   g_sel [B_*2];
__device__ float g_selw[B_*2];

// ---------------- kernel 1: global average pool ----------------
__global__ void gap_kernel(const float* __restrict__ x) {
    int bc = blockIdx.x;                       // 0 .. B*C-1
    const float4* p = (const float4*)(x + (size_t)bc * HW_);
    float s = 0.f;
    for (int i = threadIdx.x; i < HW_/4; i += 256) {
        float4 v = p[i];
        s += v.x + v.y + v.z + v.w;
    }
    __shared__ float red[256];
    red[threadIdx.x] = s;
    __syncthreads();
    for (int off = 128; off > 0; off >>= 1) {
        if (threadIdx.x < off) red[threadIdx.x] += red[threadIdx.x + off];
        __syncthreads();
    }
    if (threadIdx.x == 0) g_gap[bc] = red[0] * (1.f / HW_);
}

// ---------------- kernel 2: gate (softmax, top-2, renorm, aux loss) ----------------
__global__ void gate_kernel(const float* __restrict__ gw, const float* __restrict__ gb,
                            float* __restrict__ aux_out, int has_aux) {
    __shared__ int   sel_s[B_][2];
    __shared__ float w_s[B_][2];
    int lane = threadIdx.x;
    if (lane < B_) {
        float l[E_];
        #pragma unroll
        for (int e = 0; e < E_; e++) {
            float s = gb[e];
            for (int c = 0; c < C_; c++) s += g_gap[lane*C_ + c] * gw[e*C_ + c];
            l[e] = s;
        }
        float m = l[0];
        #pragma unroll
        for (int e = 1; e < E_; e++) m = fmaxf(m, l[e]);
        float p[E_], sum = 0.f;
        #pragma unroll
        for (int e = 0; e < E_; e++) { p[e] = expf(l[e] - m); sum += p[e]; }
        #pragma unroll
        for (int e = 0; e < E_; e++) p[e] /= sum;
        // top-2 with first-occurrence tie-break (matches jax.lax.top_k)
        int i1 = 0;
        #pragma unroll
        for (int e = 1; e < E_; e++) if (p[e] > p[i1]) i1 = e;
        int i2 = -1;
        #pragma unroll
        for (int e = 0; e < E_; e++) {
            if (e == i1) continue;
            if (i2 < 0 || p[e] > p[i2]) i2 = e;
        }
        float denom = p[i1] + p[i2] + 1e-8f;
        float w1 = p[i1] / denom, w2 = p[i2] / denom;
        g_sel[lane*2]  = i1;  g_sel[lane*2+1]  = i2;
        g_selw[lane*2] = w1;  g_selw[lane*2+1] = w2;
        sel_s[lane][0] = i1;  sel_s[lane][1] = i2;
        w_s[lane][0] = w1;    w_s[lane][1] = w2;
    }
    __syncthreads();
    if (lane == 0 && has_aux) {
        float usage[E_] = {0.f, 0.f, 0.f, 0.f};
        for (int b = 0; b < B_; b++) {        // deterministic serial sum
            usage[sel_s[b][0]] += w_s[b][0];
            usage[sel_s[b][1]] += w_s[b][1];
        }
        float mean = 0.f;
        #pragma unroll
        for (int e = 0; e < E_; e++) mean += usage[e];
        mean *= 0.25f;
        float var = 0.f;
        #pragma unroll
        for (int e = 0; e < E_; e++) { float d = usage[e] - mean; var += d * d; }
        var *= 0.25f;
        aux_out[0] = var / (mean * mean + 1e-10f);
    }
}

// ---------------- kernel 3: weight transpose + BN fold ----------------
__global__ void prep_kernel(const float* __restrict__ W1, const float* __restrict__ b1,
                            const float* __restrict__ g1, const float* __restrict__ be1,
                            const float* __restrict__ m1, const float* __restrict__ v1,
                            const float* __restrict__ W2, const float* __restrict__ b2,
                            const float* __restrict__ g2, const float* __restrict__ be2,
                            const float* __restrict__ m2, const float* __restrict__ v2,
                            const float* __restrict__ W3) {
    int idx = blockIdx.x * 256 + threadIdx.x;     // launched with >= E*HID*HID threads
    if (idx < E_*HID_*HID_) {                     // W2T: [e][o][i] -> [e][i][o] * inv2
        int e = idx / (HID_*HID_);
        int r = idx - e*HID_*HID_;
        int o = r / HID_, i = r % HID_;
        float inv = g2[e*HID_+o] / sqrtf(v2[e*HID_+o] + BN_EPS_);
        g_W2T[(e*HID_ + i)*HID_ + o] = W2[idx] * inv;
    }
    if (idx < E_*HID_*C_) {                       // W1T: [e][o][c] -> [e][c][o] * inv1
        int e = idx / (HID_*C_);
        int r = idx - e*HID_*C_;
        int o = r / C_, c = r % C_;
        float inv = g1[e*HID_+o] / sqrtf(v1[e*HID_+o] + BN_EPS_);
        g_W1T[(e*C_ + c)*HID_ + o] = W1[idx] * inv;
    }
    if (idx < E_*C_*HID_) {                       // W3T: [e][ch][i] -> [e][i][ch]
        int e = idx / (C_*HID_);
        int r = idx - e*C_*HID_;
        int ch = r / HID_, i = r % HID_;
        g_W3T[(e*HID_ + i)*C_ + ch] = W3[idx];
    }
    if (idx < E_*HID_) {                          // fused biases
        float inv1 = g1[idx] / sqrtf(v1[idx] + BN_EPS_);
        g_t1[idx] = (b1[idx] - m1[idx]) * inv1 + be1[idx];
        float inv2 = g2[idx] / sqrtf(v2[idx] + BN_EPS_);
        g_t2[idx] = (b2[idx] - m2[idx]) * inv2 + be2[idx];
    }
}

// ---------------- main fused 3-layer MoE kernel (512 threads) ----------------
// 512 threads: thread grid 16(n,pixels) x 32(m,rows).
// Layers 1-2: per-thread 4x8 fragment of the 128x128 output.
// Layer 3:    per-thread 2x8 fragment of the 64x128 output.
// All operands in smem with immediate-offset LDS (keeps alu-pipe cold).

#define LOAD_F4(dst, src) { float4 _t = *(const float4*)(src); \
    (dst)[0]=_t.x; (dst)[1]=_t.y; (dst)[2]=_t.z; (dst)[3]=_t.w; }

// 128 x TP output: A smem [K][HID_] (M contiguous), B smem [K][TP]
template<int K>
__device__ __forceinline__ void gemm128(const float* __restrict__ A,
                                        const float* __restrict__ Bm,
                                        float* __restrict__ Hout,
                                        const float* __restrict__ bias,
                                        int tx, int ty) {
    float acc[4][8];
    #pragma unroll
    for (int m = 0; m < 4; m++)
        #pragma unroll
        for (int n = 0; n < 8; n++) acc[m][n] = 0.f;

    #pragma unroll 8
    for (int k = 0; k < K; k++) {
        float a[4], bb[8];
        LOAD_F4(a,      &A[k*HID_ + ty*4]);
        LOAD_F4(bb,     &Bm[k*TP + tx*8]);
        LOAD_F4(bb + 4, &Bm[k*TP + tx*8 + 4]);
        #pragma unroll
        for (int m = 0; m < 4; m++)
            #pragma unroll
            for (int n = 0; n < 8; n++)
                acc[m][n] = fmaf(a[m], bb[n], acc[m][n]);
    }
    #pragma unroll
    for (int m = 0; m < 4; m++) {
        int o = ty*4 + m;
        float bv = bias[o];
        float4 r0, r1;
        r0.x = fmaxf(acc[m][0] + bv, 0.f);
        r0.y = fmaxf(acc[m][1] + bv, 0.f);
        r0.z = fmaxf(acc[m][2] + bv, 0.f);
        r0.w = fmaxf(acc[m][3] + bv, 0.f);
        r1.x = fmaxf(acc[m][4] + bv, 0.f);
        r1.y = fmaxf(acc[m][5] + bv, 0.f);
        r1.z = fmaxf(acc[m][6] + bv, 0.f);
        r1.w = fmaxf(acc[m][7] + bv, 0.f);
        *(float4*)&Hout[o*TP + tx*8]     = r0;
        *(float4*)&Hout[o*TP + tx*8 + 4] = r1;
    }
}

__global__ void __launch_bounds__(NT, 1)
moe_main(const float* __restrict__ x, const float* __restrict__ b3,
         float* __restrict__ out) {
    extern __shared__ float sm[];
    float* Xs = sm;                    // 64  * 128  (32 KB)
    float* Ws = Xs + C_*TP;            // up to 128*128 (64 KB)
    float* H1 = Ws + HID_*HID_;        // 128 * 128  (64 KB)
    float* H2 = H1 + HID_*TP;          // 128 * 128  (64 KB)

    const int tid = threadIdx.x;
    const int tx  = tid & 15;          // pixel group (8 pixels)
    const int ty  = tid >> 4;          // 0..31, row group
    const int b   = blockIdx.y;
    const int p0  = blockIdx.x * TP;

    // ---- load X tile: Xs[c][p] (coalesced float4) ----
    {
        const float4* xg = (const float4*)(x + (size_t)b * C_ * HW_);
        int base4 = p0 >> 2;
        #pragma unroll
        for (int i = tid; i < C_*TP/4; i += NT) {
            int c = i >> 5;            // TP/4 = 32 float4 per row
            int j = i & 31;
            ((float4*)Xs)[i] = xg[(size_t)c*(HW_/4) + base4 + j];
        }
    }

    float oacc[2][8];
    #pragma unroll
    for (int m = 0; m < 2; m++)
        #pragma unroll
        for (int n = 0; n < 8; n++) oacc[m][n] = 0.f;

    #pragma unroll 1
    for (int s = 0; s < 2; s++) {
        int   e    = g_sel[b*2 + s];
        float gwgt = g_selw[b*2 + s];

        __syncthreads();   // protect Ws/H2 reads from previous iteration; X load done
        // ---- stage W1T (32KB) ----
        {
            const float4* wg = (const float4*)(g_W1T + e*C_*HID_);
            #pragma unroll
            for (int i = tid; i < C_*HID_/4; i += NT) ((float4*)Ws)[i] = wg[i];
        }
        __syncthreads();
        // ---- layer 1: H1 = relu(W1s @ X + t1) ----
        gemm128<C_>(Ws, Xs, H1, g_t1 + e*HID_, tx, ty);
        __syncthreads();
        // ---- stage W2T (64KB) ----
        {
            const float4* wg = (const float4*)(g_W2T + e*HID_*HID_);
            #pragma unroll
            for (int i = tid; i < HID_*HID_/4; i += NT) ((float4*)Ws)[i] = wg[i];
        }
        __syncthreads();
        // ---- layer 2: H2 = relu(W2s @ H1 + t2) ----
        gemm128<HID_>(Ws, H1, H2, g_t2 + e*HID_, tx, ty);
        __syncthreads();
        // ---- stage W3T (32KB) ----
        {
            const float4* wg = (const float4*)(g_W3T + e*HID_*C_);
            #pragma unroll
            for (int i = tid; i < HID_*C_/4; i += NT) ((float4*)Ws)[i] = wg[i];
        }
        __syncthreads();
        // ---- layer 3: oacc += gwgt * (W3 @ H2 + b3), 2x8 fragment ----
        {
            float acc[2][8];
            #pragma unroll
            for (int m = 0; m < 2; m++)
                #pragma unroll
                for (int n = 0; n < 8; n++) acc[m][n] = 0.f;

            #pragma unroll 8
            for (int k = 0; k < HID_; k++) {
                float2 av = *(const float2*)&Ws[k*C_ + ty*2];
                float bb[8];
                LOAD_F4(bb,     &H2[k*TP + tx*8]);
                LOAD_F4(bb + 4, &H2[k*TP + tx*8 + 4]);
                #pragma unroll
                for (int n = 0; n < 8; n++) {
                    acc[0][n] = fmaf(av.x, bb[n], acc[0][n]);
                    acc[1][n] = fmaf(av.y, bb[n], acc[1][n]);
                }
            }
            const float* b3p = b3 + e*C_;
            #pragma unroll
            for (int m = 0; m < 2; m++) {
                float bias = b3p[ty*2 + m];
                #pragma unroll
                for (int n = 0; n < 8; n++)
                    oacc[m][n] = fmaf(gwgt, acc[m][n] + bias, oacc[m][n]);
            }
        }
    }

    // ---- store output tile: out[b][ch][p0 + ...] ----
    float* og = out + (size_t)b * C_ * HW_ + p0;
    #pragma unroll
    for (int m = 0; m < 2; m++) {
        int ch = ty*2 + m;
        float4 r0, r1;
        r0.x = oacc[m][0]; r0.y = oacc[m][1]; r0.z = oacc[m][2]; r0.w = oacc[m][3];
        r1.x = oacc[m][4]; r1.y = oacc[m][5]; r1.z = oacc[m][6]; r1.w = oacc[m][7];
        *(float4*)&og[(size_t)ch*HW_ + tx*8]     = r0;
        *(float4*)&og[(size_t)ch*HW_ + tx*8 + 4] = r1;
    }
}

// ---------------- launch ----------------
extern "C" void kernel_launch(void* const* d_in, const int* in_sizes, int n_in,
                              void* d_out, int out_size) {
    const float* x   = (const float*)d_in[0];
    const float* W1  = (const float*)d_in[1];
    const float* b1  = (const float*)d_in[2];
    const float* g1  = (const float*)d_in[3];
    const float* be1 = (const float*)d_in[4];
    const float* m1  = (const float*)d_in[5];
    const float* v1  = (const float*)d_in[6];
    const float* W2  = (const float*)d_in[7];
    const float* b2  = (const float*)d_in[8];
    const float* g2  = (const float*)d_in[9];
    const float* be2 = (const float*)d_in[10];
    const float* v2  = (const float*)d_in[12];
    const float* m2  = (const float*)d_in[11];
    const float* W3  = (const float*)d_in[13];
    const float* b3  = (const float*)d_in[14];
    const float* gw  = (const float*)d_in[15];
    const float* gb  = (const float*)d_in[16];
    float* out = (float*)d_out;

    const int SMEM = (C_*TP + 3*HID_*HID_) * 4;    // 229376 bytes
    cudaFuncSetAttribute(moe_main, cudaFuncAttributeMaxDynamicSharedMemorySize, SMEM);

    gap_kernel<<<B_*C_, 256>>>(x);

    prep_kernel<<<(E_*HID_*HID_ + 255) / 256, 256>>>(
        W1, b1, g1, be1, m1, v1, W2, b2, g2, be2, m2, v2, W3);

    const int N = B_ * C_ * HW_;
    int has_aux = (out_size > N) ? 1 : 0;
    gate_kernel<<<1, 32>>>(gw, gb, out + N, has_aux);

    dim3 grid(HW_ / TP, B_);
    moe_main<<<grid, NT, SMEM>>>(x, b3, out);
}

// round 10
// speedup vs baseline: 2.6523x; 2.6523x over previous
#include <cuda_runtime.h>
#include <math.h>

#define E_    4
#define C_    64
#define HID_  128
#define B_    16
#define HW_   16384      // 128*128
#define TP    128        // pixels per tile
#define BN_EPS_ 1e-5f

typedef unsigned long long u64t;

// ---------------- device scratch (no allocs allowed) ----------------
__device__ float g_W1T[E_*C_*HID_];     // [e][c][o]   (BN scale folded)
__device__ float g_t1 [E_*HID_];        // fused bias layer1
__device__ float g_W2T[E_*HID_*HID_];   // [e][i][o]   (BN scale folded)
__device__ float g_t2 [E_*HID_];
__device__ float g_W3T[E_*HID_*C_];     // [e][i][ch]
__device__ float g_gap[B_*C_];
__device__ int   g_sel [B_*2];
__device__ float g_selw[B_*2];

// ---------------- packed f32x2 helpers (sm_103a) ----------------
__device__ __forceinline__ u64t dup2f(float v) {
    u64t r;
    asm("mov.b64 %0, {%1, %1};" : "=l"(r) : "r"(__float_as_uint(v)));
    return r;
}
__device__ __forceinline__ void fma2(u64t& d, u64t a, u64t b) {
    asm("fma.rn.f32x2 %0, %1, %2, %3;" : "=l"(d) : "l"(a), "l"(b), "l"(d));
}
__device__ __forceinline__ u64t add2(u64t a, u64t b) {
    u64t d;
    asm("add.rn.f32x2 %0, %1, %2;" : "=l"(d) : "l"(a), "l"(b));
    return d;
}
__device__ __forceinline__ float2 unp2(u64t p) {
    float lo, hi;
    asm("mov.b64 {%0, %1}, %2;" : "=f"(lo), "=f"(hi) : "l"(p));
    return make_float2(lo, hi);
}

// ---------------- kernel 1: global average pool ----------------
__global__ void gap_kernel(const float* __restrict__ x) {
    int bc = blockIdx.x;                       // 0 .. B*C-1
    const float4* p = (const float4*)(x + (size_t)bc * HW_);
    float s = 0.f;
    for (int i = threadIdx.x; i < HW_/4; i += 256) {
        float4 v = p[i];
        s += v.x + v.y + v.z + v.w;
    }
    __shared__ float red[256];
    red[threadIdx.x] = s;
    __syncthreads();
    for (int off = 128; off > 0; off >>= 1) {
        if (threadIdx.x < off) red[threadIdx.x] += red[threadIdx.x + off];
        __syncthreads();
    }
    if (threadIdx.x == 0) g_gap[bc] = red[0] * (1.f / HW_);
}

// ---------------- kernel 2: gate (softmax, top-2, renorm, aux loss) ----------------
__global__ void gate_kernel(const float* __restrict__ gw, const float* __restrict__ gb,
                            float* __restrict__ aux_out, int has_aux) {
    __shared__ int   sel_s[B_][2];
    __shared__ float w_s[B_][2];
    int lane = threadIdx.x;
    if (lane < B_) {
        float l[E_];
        #pragma unroll
        for (int e = 0; e < E_; e++) {
            float s = gb[e];
            for (int c = 0; c < C_; c++) s += g_gap[lane*C_ + c] * gw[e*C_ + c];
            l[e] = s;
        }
        float m = l[0];
        #pragma unroll
        for (int e = 1; e < E_; e++) m = fmaxf(m, l[e]);
        float p[E_], sum = 0.f;
        #pragma unroll
        for (int e = 0; e < E_; e++) { p[e] = expf(l[e] - m); sum += p[e]; }
        #pragma unroll
        for (int e = 0; e < E_; e++) p[e] /= sum;
        // top-2 with first-occurrence tie-break (matches jax.lax.top_k)
        int i1 = 0;
        #pragma unroll
        for (int e = 1; e < E_; e++) if (p[e] > p[i1]) i1 = e;
        int i2 = -1;
        #pragma unroll
        for (int e = 0; e < E_; e++) {
            if (e == i1) continue;
            if (i2 < 0 || p[e] > p[i2]) i2 = e;
        }
        float denom = p[i1] + p[i2] + 1e-8f;
        float w1 = p[i1] / denom, w2 = p[i2] / denom;
        g_sel[lane*2]  = i1;  g_sel[lane*2+1]  = i2;
        g_selw[lane*2] = w1;  g_selw[lane*2+1] = w2;
        sel_s[lane][0] = i1;  sel_s[lane][1] = i2;
        w_s[lane][0] = w1;    w_s[lane][1] = w2;
    }
    __syncthreads();
    if (lane == 0 && has_aux) {
        float usage[E_] = {0.f, 0.f, 0.f, 0.f};
        for (int b = 0; b < B_; b++) {        // deterministic serial sum
            usage[sel_s[b][0]] += w_s[b][0];
            usage[sel_s[b][1]] += w_s[b][1];
        }
        float mean = 0.f;
        #pragma unroll
        for (int e = 0; e < E_; e++) mean += usage[e];
        mean *= 0.25f;
        float var = 0.f;
        #pragma unroll
        for (int e = 0; e < E_; e++) { float d = usage[e] - mean; var += d * d; }
        var *= 0.25f;
        aux_out[0] = var / (mean * mean + 1e-10f);
    }
}

// ---------------- kernel 3: weight transpose + BN fold ----------------
__global__ void prep_kernel(const float* __restrict__ W1, const float* __restrict__ b1,
                            const float* __restrict__ g1, const float* __restrict__ be1,
                            const float* __restrict__ m1, const float* __restrict__ v1,
                            const float* __restrict__ W2, const float* __restrict__ b2,
                            const float* __restrict__ g2, const float* __restrict__ be2,
                            const float* __restrict__ m2, const float* __restrict__ v2,
                            const float* __restrict__ W3) {
    int idx = blockIdx.x * 256 + threadIdx.x;     // launched with >= E*HID*HID threads
    if (idx < E_*HID_*HID_) {                     // W2T: [e][o][i] -> [e][i][o] * inv2
        int e = idx / (HID_*HID_);
        int r = idx - e*HID_*HID_;
        int o = r / HID_, i = r % HID_;
        float inv = g2[e*HID_+o] / sqrtf(v2[e*HID_+o] + BN_EPS_);
        g_W2T[(e*HID_ + i)*HID_ + o] = W2[idx] * inv;
    }
    if (idx < E_*HID_*C_) {                       // W1T: [e][o][c] -> [e][c][o] * inv1
        int e = idx / (HID_*C_);
        int r = idx - e*HID_*C_;
        int o = r / C_, c = r % C_;
        float inv = g1[e*HID_+o] / sqrtf(v1[e*HID_+o] + BN_EPS_);
        g_W1T[(e*C_ + c)*HID_ + o] = W1[idx] * inv;
    }
    if (idx < E_*C_*HID_) {                       // W3T: [e][ch][i] -> [e][i][ch]
        int e = idx / (C_*HID_);
        int r = idx - e*C_*HID_;
        int ch = r / HID_, i = r % HID_;
        g_W3T[(e*HID_ + i)*C_ + ch] = W3[idx];
    }
    if (idx < E_*HID_) {                          // fused biases
        float inv1 = g1[idx] / sqrtf(v1[idx] + BN_EPS_);
        g_t1[idx] = (b1[idx] - m1[idx]) * inv1 + be1[idx];
        float inv2 = g2[idx] / sqrtf(v2[idx] + BN_EPS_);
        g_t2[idx] = (b2[idx] - m2[idx]) * inv2 + be2[idx];
    }
}

// ---------------- main fused 3-layer MoE kernel (256 thr, f32x2 FMA) ----------------
#define LOAD_F4(dst, src) { float4 _t = *(const float4*)(src); \
    (dst)[0]=_t.x; (dst)[1]=_t.y; (dst)[2]=_t.z; (dst)[3]=_t.w; }

// 128 x TP output: A smem [K][HID_] (M contiguous), B smem [K][TP]
// 8x8 fragment held as 8x4 f32x2 pairs (paired along n).
template<int K>
__device__ __forceinline__ void gemm128(const float* __restrict__ A,
                                        const float* __restrict__ Bm,
                                        float* __restrict__ Hout,
                                        const float* __restrict__ bias,
                                        int tx, int ty) {
    u64t acc[8][4];
    #pragma unroll
    for (int m = 0; m < 8; m++)
        #pragma unroll
        for (int n = 0; n < 4; n++) acc[m][n] = 0ULL;

    #pragma unroll 4
    for (int k = 0; k < K; k++) {
        float a[8];
        LOAD_F4(a,     &A[k*HID_ + ty*8]);
        LOAD_F4(a + 4, &A[k*HID_ + ty*8 + 4]);
        ulonglong2 b01 = *(const ulonglong2*)&Bm[k*TP + tx*8];
        ulonglong2 b23 = *(const ulonglong2*)&Bm[k*TP + tx*8 + 4];
        u64t bp0 = b01.x, bp1 = b01.y, bp2 = b23.x, bp3 = b23.y;
        #pragma unroll
        for (int m = 0; m < 8; m++) {
            u64t ad = dup2f(a[m]);
            fma2(acc[m][0], ad, bp0);
            fma2(acc[m][1], ad, bp1);
            fma2(acc[m][2], ad, bp2);
            fma2(acc[m][3], ad, bp3);
        }
    }
    #pragma unroll
    for (int m = 0; m < 8; m++) {
        int o = ty*8 + m;
        float bv = bias[o];
        float2 v0 = unp2(acc[m][0]);
        float2 v1 = unp2(acc[m][1]);
        float2 v2 = unp2(acc[m][2]);
        float2 v3 = unp2(acc[m][3]);
        float4 r0, r1;
        r0.x = fmaxf(v0.x + bv, 0.f); r0.y = fmaxf(v0.y + bv, 0.f);
        r0.z = fmaxf(v1.x + bv, 0.f); r0.w = fmaxf(v1.y + bv, 0.f);
        r1.x = fmaxf(v2.x + bv, 0.f); r1.y = fmaxf(v2.y + bv, 0.f);
        r1.z = fmaxf(v3.x + bv, 0.f); r1.w = fmaxf(v3.y + bv, 0.f);
        *(float4*)&Hout[o*TP + tx*8]     = r0;
        *(float4*)&Hout[o*TP + tx*8 + 4] = r1;
    }
}

__global__ void __launch_bounds__(256, 1)
moe_main(const float* __restrict__ x, const float* __restrict__ b3,
         float* __restrict__ out) {
    extern __shared__ float sm[];
    float* Xs = sm;                    // 64 * 128
    float* Ws = Xs + C_*TP;            // up to 128 * 128
    float* H1 = Ws + HID_*HID_;        // 128 * 128
    float* H2 = H1 + HID_*TP;          // 128 * 128

    const int tid = threadIdx.x;
    const int tx  = tid & 15;
    const int ty  = tid >> 4;
    const int b   = blockIdx.y;
    const int p0  = blockIdx.x * TP;

    // ---- load X tile: Xs[c][p] (coalesced float4) ----
    {
        const float4* xg = (const float4*)(x + (size_t)b * C_ * HW_);
        int base4 = p0 >> 2;
        #pragma unroll
        for (int i = tid; i < C_*TP/4; i += 256) {
            int c = i >> 5;            // TP/4 = 32 float4 per row
            int j = i & 31;
            ((float4*)Xs)[i] = xg[(size_t)c*(HW_/4) + base4 + j];
        }
    }

    u64t oacc[4][4];                   // 4x8 output fragment as f32x2 pairs
    #pragma unroll
    for (int m = 0; m < 4; m++)
        #pragma unroll
        for (int n = 0; n < 4; n++) oacc[m][n] = 0ULL;

    #pragma unroll 1
    for (int s = 0; s < 2; s++) {
        int   e    = g_sel[b*2 + s];
        float gwgt = g_selw[b*2 + s];

        __syncthreads();   // protect Ws/H2 reads from previous iteration; X load done
        // ---- stage W1T (32KB) ----
        {
            const float4* wg = (const float4*)(g_W1T + e*C_*HID_);
            for (int i = tid; i < C_*HID_/4; i += 256) ((float4*)Ws)[i] = wg[i];
        }
        __syncthreads();
        // ---- layer 1: H1 = relu(W1s @ X + t1) ----
        gemm128<C_>(Ws, Xs, H1, g_t1 + e*HID_, tx, ty);
        __syncthreads();
        // ---- stage W2T (64KB) ----
        {
            const float4* wg = (const float4*)(g_W2T + e*HID_*HID_);
            for (int i = tid; i < HID_*HID_/4; i += 256) ((float4*)Ws)[i] = wg[i];
        }
        __syncthreads();
        // ---- layer 2: H2 = relu(W2s @ H1 + t2) ----
        gemm128<HID_>(Ws, H1, H2, g_t2 + e*HID_, tx, ty);
        __syncthreads();
        // ---- stage W3T (32KB) ----
        {
            const float4* wg = (const float4*)(g_W3T + e*HID_*C_);
            for (int i = tid; i < HID_*C_/4; i += 256) ((float4*)Ws)[i] = wg[i];
        }
        __syncthreads();
        // ---- layer 3: oacc += gwgt * (W3 @ H2 + b3), 4x8 fragment (f32x2) ----
        {
            u64t acc[4][4];
            #pragma unroll
            for (int m = 0; m < 4; m++)
                #pragma unroll
                for (int n = 0; n < 4; n++) acc[m][n] = 0ULL;

            #pragma unroll 4
            for (int k = 0; k < HID_; k++) {
                float a[4];
                LOAD_F4(a, &Ws[k*C_ + ty*4]);
                ulonglong2 b01 = *(const ulonglong2*)&H2[k*TP + tx*8];
                ulonglong2 b23 = *(const ulonglong2*)&H2[k*TP + tx*8 + 4];
                u64t bp0 = b01.x, bp1 = b01.y, bp2 = b23.x, bp3 = b23.y;
                #pragma unroll
                for (int m = 0; m < 4; m++) {
                    u64t ad = dup2f(a[m]);
                    fma2(acc[m][0], ad, bp0);
                    fma2(acc[m][1], ad, bp1);
                    fma2(acc[m][2], ad, bp2);
                    fma2(acc[m][3], ad, bp3);
                }
            }
            const float* b3p = b3 + e*C_;
            u64t gd = dup2f(gwgt);
            #pragma unroll
            for (int m = 0; m < 4; m++) {
                u64t bd = dup2f(b3p[ty*4 + m]);
                #pragma unroll
                for (int n = 0; n < 4; n++)
                    fma2(oacc[m][n], gd, add2(acc[m][n], bd));
            }
        }
    }

    // ---- store output tile: out[b][ch][p0 + ...] ----
    float* og = out + (size_t)b * C_ * HW_ + p0;
    #pragma unroll
    for (int m = 0; m < 4; m++) {
        int ch = ty*4 + m;
        float2 v0 = unp2(oacc[m][0]);
        float2 v1 = unp2(oacc[m][1]);
        float2 v2 = unp2(oacc[m][2]);
        float2 v3 = unp2(oacc[m][3]);
        float4 r0, r1;
        r0.x = v0.x; r0.y = v0.y; r0.z = v1.x; r0.w = v1.y;
        r1.x = v2.x; r1.y = v2.y; r1.z = v3.x; r1.w = v3.y;
        *(float4*)&og[(size_t)ch*HW_ + tx*8]     = r0;
        *(float4*)&og[(size_t)ch*HW_ + tx*8 + 4] = r1;
    }
}

// ---------------- launch ----------------
extern "C" void kernel_launch(void* const* d_in, const int* in_sizes, int n_in,
                              void* d_out, int out_size) {
    const float* x   = (const float*)d_in[0];
    const float* W1  = (const float*)d_in[1];
    const float* b1  = (const float*)d_in[2];
    const float* g1  = (const float*)d_in[3];
    const float* be1 = (const float*)d_in[4];
    const float* m1  = (const float*)d_in[5];
    const float* v1  = (const float*)d_in[6];
    const float* W2  = (const float*)d_in[7];
    const float* b2  = (const float*)d_in[8];
    const float* g2  = (const float*)d_in[9];
    const float* be2 = (const float*)d_in[10];
    const float* m2  = (const float*)d_in[11];
    const float* v2  = (const float*)d_in[12];
    const float* W3  = (const float*)d_in[13];
    const float* b3  = (const float*)d_in[14];
    const float* gw  = (const float*)d_in[15];
    const float* gb  = (const float*)d_in[16];
    float* out = (float*)d_out;

    const int SMEM = (C_*TP + 3*HID_*HID_) * 4;    // 229376 bytes
    cudaFuncSetAttribute(moe_main, cudaFuncAttributeMaxDynamicSharedMemorySize, SMEM);

    gap_kernel<<<B_*C_, 256>>>(x);

    prep_kernel<<<(E_*HID_*HID_ + 255) / 256, 256>>>(
        W1, b1, g1, be1, m1, v1, W2, b2, g2, be2, m2, v2, W3);

    const int N = B_ * C_ * HW_;
    int has_aux = (out_size > N) ? 1 : 0;
    gate_kernel<<<1, 32>>>(gw, gb, out + N, has_aux);

    dim3 grid(HW_ / TP, B_);
    moe_main<<<grid, 256, SMEM>>>(x, b3, out);
}

// round 15
// speedup vs baseline: 5.2582x; 1.9825x over previous
#include <cuda_runtime.h>
#include <cuda_bf16.h>
#include <math.h>
#include <stdint.h>

#define E_    4
#define C_    64
#define HID_  128
#define B_    16
#define HW_   16384      // 128*128
#define TP    128        // pixels per tile
#define BN_EPS_ 1e-5f

// image pitches (bytes). 144 = 9*16, 272 = 17*16 -> LDSM bank-conflict-free, 16B rows
#define P64   144
#define P128  272
#define W1IMG 18432      // 128 rows * 144
#define W2IMG 34816      // 128 rows * 272
#define W3IMG 17408      // 64  rows * 272

// smem layout (bytes)
#define SM_X   0
#define XIMG   18432     // 128 pixels * 144 (K=64)
#define SM_H   36864
#define HIMG   34816     // 128 pixels * 272 (K=128)
#define SM_W   106496
#define SMEMSZ (SM_W + 2*W2IMG)   // 176128

// ================= device scratch (no allocs allowed) =================
__device__ uint4 g_w1[E_][2*W1IMG/16];   // [hi img][lo img], rows=o(128), k=c(64)
__device__ uint4 g_w2[E_][2*W2IMG/16];   // rows=o(128), k=i(128)
__device__ uint4 g_w3[E_][2*W3IMG/16];   // rows=c(64),  k=i(128)
__device__ float g_t1 [E_*HID_];
__device__ float g_t2 [E_*HID_];
__device__ float g_gap[B_*C_];
__device__ int   g_sel [B_*2];
__device__ float g_selw[B_*2];

// ================= PTX primitives (baseline ISA, compute_103-safe) =================
__device__ __forceinline__ uint32_t smem_u32(const void* p) {
    uint32_t a;
    asm("{ .reg .u64 t; cvta.to.shared.u64 t, %1; cvt.u32.u64 %0, t; }" : "=r"(a) : "l"(p));
    return a;
}
__device__ __forceinline__ void ldsm_x4(uint32_t* r, uint32_t addr) {
    asm volatile("ldmatrix.sync.aligned.m8n8.x4.shared.b16 {%0,%1,%2,%3}, [%4];"
        : "=r"(r[0]), "=r"(r[1]), "=r"(r[2]), "=r"(r[3]) : "r"(addr));
}
__device__ __forceinline__ void mma16816(float* d, const uint32_t* a, const uint32_t* b) {
    asm volatile("mma.sync.aligned.m16n8k16.row.col.f32.bf16.bf16.f32 "
        "{%0,%1,%2,%3}, {%4,%5,%6,%7}, {%8,%9}, {%0,%1,%2,%3};"
        : "+f"(d[0]), "+f"(d[1]), "+f"(d[2]), "+f"(d[3])
        : "r"(a[0]), "r"(a[1]), "r"(a[2]), "r"(a[3]), "r"(b[0]), "r"(b[1]));
}
__device__ __forceinline__ uint32_t pack_bf2(__nv_bfloat16 a, __nv_bfloat16 b) {
    return (uint32_t)__bfloat16_as_ushort(a) | ((uint32_t)__bfloat16_as_ushort(b) << 16);
}

// ================= kernel 1: global average pool =================
__global__ void gap_kernel(const float* __restrict__ x) {
    int bc = blockIdx.x;
    const float4* p = (const float4*)(x + (size_t)bc * HW_);
    float s = 0.f;
    for (int i = threadIdx.x; i < HW_/4; i += 256) {
        float4 v = p[i];
        s += v.x + v.y + v.z + v.w;
    }
    __shared__ float red[256];
    red[threadIdx.x] = s;
    __syncthreads();
    for (int off = 128; off > 0; off >>= 1) {
        if (threadIdx.x < off) red[threadIdx.x] += red[threadIdx.x + off];
        __syncthreads();
    }
    if (threadIdx.x == 0) g_gap[bc] = red[0] * (1.f / HW_);
}

// ================= kernel 2: gate =================
__global__ void gate_kernel(const float* __restrict__ gw, const float* __restrict__ gb,
                            float* __restrict__ aux_out, int has_aux) {
    __shared__ int   sel_s[B_][2];
    __shared__ float w_s[B_][2];
    int lane = threadIdx.x;
    if (lane < B_) {
        float l[E_];
        #pragma unroll
        for (int e = 0; e < E_; e++) {
            float s = gb[e];
            for (int c = 0; c < C_; c++) s += g_gap[lane*C_ + c] * gw[e*C_ + c];
            l[e] = s;
        }
        float m = l[0];
        #pragma unroll
        for (int e = 1; e < E_; e++) m = fmaxf(m, l[e]);
        float p[E_], sum = 0.f;
        #pragma unroll
        for (int e = 0; e < E_; e++) { p[e] = expf(l[e] - m); sum += p[e]; }
        #pragma unroll
        for (int e = 0; e < E_; e++) p[e] /= sum;
        int i1 = 0;
        #pragma unroll
        for (int e = 1; e < E_; e++) if (p[e] > p[i1]) i1 = e;
        int i2 = -1;
        #pragma unroll
        for (int e = 0; e < E_; e++) {
            if (e == i1) continue;
            if (i2 < 0 || p[e] > p[i2]) i2 = e;
        }
        float denom = p[i1] + p[i2] + 1e-8f;
        float w1 = p[i1] / denom, w2 = p[i2] / denom;
        g_sel[lane*2]  = i1;  g_sel[lane*2+1]  = i2;
        g_selw[lane*2] = w1;  g_selw[lane*2+1] = w2;
        sel_s[lane][0] = i1;  sel_s[lane][1] = i2;
        w_s[lane][0] = w1;    w_s[lane][1] = w2;
    }
    __syncthreads();
    if (lane == 0 && has_aux) {
        float usage[E_] = {0.f, 0.f, 0.f, 0.f};
        for (int b = 0; b < B_; b++) {
            usage[sel_s[b][0]] += w_s[b][0];
            usage[sel_s[b][1]] += w_s[b][1];
        }
        float mean = 0.f;
        #pragma unroll
        for (int e = 0; e < E_; e++) mean += usage[e];
        mean *= 0.25f;
        float var = 0.f;
        #pragma unroll
        for (int e = 0; e < E_; e++) { float d = usage[e] - mean; var += d * d; }
        var *= 0.25f;
        aux_out[0] = var / (mean * mean + 1e-10f);
    }
}

// ================= kernel 3: weight prep (BN fold + bf16 hi/lo padded images) =========
__device__ __forceinline__ void split_st(unsigned char* img, int off, int lo_off, float v) {
    __nv_bfloat16 h = __float2bfloat16(v);
    __nv_bfloat16 l = __float2bfloat16(v - __bfloat162float(h));
    *(__nv_bfloat16*)(img + off)          = h;
    *(__nv_bfloat16*)(img + lo_off + off) = l;
}

__global__ void prep_kernel(const float* __restrict__ W1, const float* __restrict__ b1,
                            const float* __restrict__ g1, const float* __restrict__ be1,
                            const float* __restrict__ m1, const float* __restrict__ v1,
                            const float* __restrict__ W2, const float* __restrict__ b2,
                            const float* __restrict__ g2, const float* __restrict__ be2,
                            const float* __restrict__ m2, const float* __restrict__ v2,
                            const float* __restrict__ W3) {
    int idx = blockIdx.x * 256 + threadIdx.x;     // >= 65536 threads
    if (idx < E_*HID_*HID_) {                     // W2 [e][o][i]
        int e = idx >> 14, r = idx & 16383, o = r >> 7, k = r & 127;
        float inv = g2[e*HID_+o] * rsqrtf(v2[e*HID_+o] + BN_EPS_);
        split_st((unsigned char*)g_w2[e], o*P128 + k*2, W2IMG, W2[idx] * inv);
    }
    if (idx < E_*HID_*C_) {                       // W1 [e][o][c]
        int e = idx >> 13, r = idx & 8191, o = r >> 6, k = r & 63;
        float inv = g1[e*HID_+o] * rsqrtf(v1[e*HID_+o] + BN_EPS_);
        split_st((unsigned char*)g_w1[e], o*P64 + k*2, W1IMG, W1[idx] * inv);
    }
    if (idx < E_*C_*HID_) {                       // W3 [e][c][i]
        int e = idx >> 13, r = idx & 8191, c = r >> 7, k = r & 127;
        split_st((unsigned char*)g_w3[e], c*P128 + k*2, W3IMG, W3[idx]);
    }
    if (idx < E_*HID_) {
        float inv1 = g1[idx] * rsqrtf(v1[idx] + BN_EPS_);
        g_t1[idx] = (b1[idx] - m1[idx]) * inv1 + be1[idx];
        float inv2 = g2[idx] * rsqrtf(v2[idx] + BN_EPS_);
        g_t2[idx] = (b2[idx] - m2[idx]) * inv2 + be2[idx];
    }
}

// ================= warp GEMM: 3-term bf16 error-compensated =================
// A image [row=pixel][k] pitch ap; B image [row=ch][k] pitch bp; both hi+lo.
// BOTH operands are [row][k] with k contiguous -> NON-trans ldmatrix for A and B.
// B lane map: lanes0-7 -> n0-7 k0-7 (=b0 grp0), 8-15 -> n0-7 k8-15 (=b1 grp0),
//             16-23 -> n8-15 k0-7 (=b0 grp1), 24-31 -> n8-15 k8-15 (=b1 grp1).
template<int KCH, int NT>
__device__ __forceinline__ void warp_gemm(uint32_t aHi, uint32_t aLo, int ap,
                                          uint32_t bHi, uint32_t bLo, int bp,
                                          float (&acc)[2][NT][4], int lane) {
    uint32_t aoff = (uint32_t)(((lane & 7) + ((lane >> 3) & 1) * 8) * ap + (lane >> 4) * 16);
    uint32_t boff = (uint32_t)(((lane & 7) + ((lane >> 4) & 1) * 8) * bp + ((lane >> 3) & 1) * 16);
    #pragma unroll 1
    for (int t = 0; t < 3; t++) {
        uint32_t Ab = ((t == 2) ? aLo : aHi) + aoff;
        uint32_t Bb = ((t == 1) ? bLo : bHi) + boff;
        #pragma unroll
        for (int kc = 0; kc < KCH; kc++) {
            uint32_t a0[4], a1[4];
            ldsm_x4(a0, Ab + kc*32);
            ldsm_x4(a1, Ab + 16*ap + kc*32);
            #pragma unroll
            for (int np = 0; np < NT/2; np++) {
                uint32_t bf[4];
                ldsm_x4(bf, Bb + np*16*bp + kc*32);     // non-trans: [n][k] rows
                mma16816(acc[0][2*np],     a0, bf);
                mma16816(acc[0][2*np + 1], a0, bf + 2);
                mma16816(acc[1][2*np],     a1, bf);
                mma16816(acc[1][2*np + 1], a1, bf + 2);
            }
        }
    }
}

// Epilogue (layers 1/2): bias + relu + hi/lo bf16 split -> H image
__device__ __forceinline__ void epi_layer(const float (&acc)[2][8][4], char* smc,
                                          const float* __restrict__ bias,
                                          int pbase, int nbase, int lane) {
    int r = lane >> 2, c2 = (lane & 3) * 2;
    #pragma unroll
    for (int mt = 0; mt < 2; mt++) {
        #pragma unroll
        for (int nt = 0; nt < 8; nt++) {
            int ch = nbase + nt*8 + c2;
            float2 bv = __ldg((const float2*)(bias + ch));
            #pragma unroll
            for (int h = 0; h < 2; h++) {
                int pix = pbase + mt*16 + r + h*8;
                float v0 = fmaxf(acc[mt][nt][2*h]     + bv.x, 0.f);
                float v1 = fmaxf(acc[mt][nt][2*h + 1] + bv.y, 0.f);
                __nv_bfloat16 h0 = __float2bfloat16(v0), h1 = __float2bfloat16(v1);
                __nv_bfloat16 l0 = __float2bfloat16(v0 - __bfloat162float(h0));
                __nv_bfloat16 l1 = __float2bfloat16(v1 - __bfloat162float(h1));
                int off = pix*P128 + ch*2;
                *(uint32_t*)(smc + SM_H + off)        = pack_bf2(h0, h1);
                *(uint32_t*)(smc + SM_H + HIMG + off) = pack_bf2(l0, l1);
            }
        }
    }
}

// ================= main fused kernel =================
__global__ void __launch_bounds__(256, 1)
moe_main(const float* __restrict__ x, const float* __restrict__ b3,
         float* __restrict__ out) {
    extern __shared__ __align__(16) char smc[];
    const uint32_t smb = smem_u32(smc);
    const int tid  = threadIdx.x;
    const int wid  = tid >> 5;
    const int lane = tid & 31;
    const int wm   = wid & 3;          // M block: 32 pixels
    const int wn   = wid >> 2;         // N block
    const int pbase = wm * 32;
    const int b    = blockIdx.y;
    const int p0   = blockIdx.x * TP;
    const int r    = lane >> 2, c2 = (lane & 3) * 2;

    // ---- stage X as A image: [pixel][c] bf16 hi/lo, pitch 144 (coalesced LDG) ----
    for (int it = tid; it < 1024; it += 256) {
        int p  = it & 127;
        int cg = it >> 7;              // 8 channels per item
        const float* xp = x + (size_t)b * C_ * HW_ + (size_t)(cg * 8) * HW_ + p0 + p;
        uint32_t hw[4], lw[4];
        #pragma unroll
        for (int q = 0; q < 4; q++) {
            float v0 = __ldg(xp + (size_t)(q*2)     * HW_);
            float v1 = __ldg(xp + (size_t)(q*2 + 1) * HW_);
            __nv_bfloat16 h0 = __float2bfloat16(v0), h1 = __float2bfloat16(v1);
            __nv_bfloat16 l0 = __float2bfloat16(v0 - __bfloat162float(h0));
            __nv_bfloat16 l1 = __float2bfloat16(v1 - __bfloat162float(h1));
            hw[q] = pack_bf2(h0, h1);
            lw[q] = pack_bf2(l0, l1);
        }
        int off = p * P64 + cg * 16;
        *(uint4*)(smc + SM_X + off)        = make_uint4(hw[0], hw[1], hw[2], hw[3]);
        *(uint4*)(smc + SM_X + XIMG + off) = make_uint4(lw[0], lw[1], lw[2], lw[3]);
    }

    float oacc[2][4][4];
    #pragma unroll
    for (int mt = 0; mt < 2; mt++)
        #pragma unroll
        for (int nt = 0; nt < 4; nt++)
            #pragma unroll
            for (int j = 0; j < 4; j++) oacc[mt][nt][j] = 0.f;

    #pragma unroll 1
    for (int s = 0; s < 2; s++) {
        int   e    = g_sel[b*2 + s];
        float gwgt = g_selw[b*2 + s];

        __syncthreads();                           // prev-iter smW/H reads done; X ready
        {   // stage W1 (hi+lo, 36864 B)
            const uint4* src = g_w1[e];
            uint4* dst = (uint4*)(smc + SM_W);
            for (int i = tid; i < 2*W1IMG/16; i += 256) dst[i] = src[i];
        }
        __syncthreads();

        // ---- layer 1: H = relu(X @ W1^T + t1), K=64, N=128 ----
        {
            float acc[2][8][4];
            #pragma unroll
            for (int mt = 0; mt < 2; mt++)
                #pragma unroll
                for (int nt = 0; nt < 8; nt++)
                    #pragma unroll
                    for (int j = 0; j < 4; j++) acc[mt][nt][j] = 0.f;
            warp_gemm<4, 8>(smb + SM_X + pbase*P64, smb + SM_X + XIMG + pbase*P64, P64,
                            smb + SM_W + (wn*64)*P64, smb + SM_W + W1IMG + (wn*64)*P64, P64,
                            acc, lane);
            epi_layer(acc, smc, g_t1 + e*HID_, pbase, wn*64, lane);
        }
        __syncthreads();                           // H writes visible; W1 reads done
        {   // stage W2 (69632 B)
            const uint4* src = g_w2[e];
            uint4* dst = (uint4*)(smc + SM_W);
            for (int i = tid; i < 2*W2IMG/16; i += 256) dst[i] = src[i];
        }
        __syncthreads();

        // ---- layer 2: H = relu(H @ W2^T + t2), K=128, N=128 ----
        {
            float acc[2][8][4];
            #pragma unroll
            for (int mt = 0; mt < 2; mt++)
                #pragma unroll
                for (int nt = 0; nt < 8; nt++)
                    #pragma unroll
                    for (int j = 0; j < 4; j++) acc[mt][nt][j] = 0.f;
            warp_gemm<8, 8>(smb + SM_H + pbase*P128, smb + SM_H + HIMG + pbase*P128, P128,
                            smb + SM_W + (wn*64)*P128, smb + SM_W + W2IMG + (wn*64)*P128, P128,
                            acc, lane);
            __syncthreads();                       // ALL H reads done before overwrite
            epi_layer(acc, smc, g_t2 + e*HID_, pbase, wn*64, lane);
        }
        {   // stage W3 (34816 B) — smW reads finished at sync above
            const uint4* src = g_w3[e];
            uint4* dst = (uint4*)(smc + SM_W);
            for (int i = tid; i < 2*W3IMG/16; i += 256) dst[i] = src[i];
        }
        __syncthreads();                           // H + W3 writes visible

        // ---- layer 3: oacc += gwgt * (H @ W3^T + b3), K=128, N=64 ----
        {
            float acc[2][4][4];
            #pragma unroll
            for (int mt = 0; mt < 2; mt++)
                #pragma unroll
                for (int nt = 0; nt < 4; nt++)
                    #pragma unroll
                    for (int j = 0; j < 4; j++) acc[mt][nt][j] = 0.f;
            warp_gemm<8, 4>(smb + SM_H + pbase*P128, smb + SM_H + HIMG + pbase*P128, P128,
                            smb + SM_W + (wn*32)*P128, smb + SM_W + W3IMG + (wn*32)*P128, P128,
                            acc, lane);
            const float* bp = b3 + e * C_;
            #pragma unroll
            for (int mt = 0; mt < 2; mt++)
                #pragma unroll
                for (int nt = 0; nt < 4; nt++) {
                    int ch = wn*32 + nt*8 + c2;
                    float2 bv = __ldg((const float2*)(bp + ch));
                    oacc[mt][nt][0] = fmaf(gwgt, acc[mt][nt][0] + bv.x, oacc[mt][nt][0]);
                    oacc[mt][nt][1] = fmaf(gwgt, acc[mt][nt][1] + bv.y, oacc[mt][nt][1]);
                    oacc[mt][nt][2] = fmaf(gwgt, acc[mt][nt][2] + bv.x, oacc[mt][nt][2]);
                    oacc[mt][nt][3] = fmaf(gwgt, acc[mt][nt][3] + bv.y, oacc[mt][nt][3]);
                }
        }
    }

    // ---- store: out[b][ch][p0 + pixel] ----
    float* ob = out + (size_t)b * C_ * HW_ + p0;
    #pragma unroll
    for (int mt = 0; mt < 2; mt++)
        #pragma unroll
        for (int nt = 0; nt < 4; nt++) {
            int ch = wn*32 + nt*8 + c2;
            #pragma unroll
            for (int h = 0; h < 2; h++) {
                int pix = pbase + mt*16 + r + h*8;
                ob[(size_t)ch * HW_ + pix]       = oacc[mt][nt][2*h];
                ob[(size_t)(ch + 1) * HW_ + pix] = oacc[mt][nt][2*h + 1];
            }
        }
}

// ================= launch =================
extern "C" void kernel_launch(void* const* d_in, const int* in_sizes, int n_in,
                              void* d_out, int out_size) {
    const float* x   = (const float*)d_in[0];
    const float* W1  = (const float*)d_in[1];
    const float* b1  = (const float*)d_in[2];
    const float* g1  = (const float*)d_in[3];
    const float* be1 = (const float*)d_in[4];
    const float* m1  = (const float*)d_in[5];
    const float* v1  = (const float*)d_in[6];
    const float* W2  = (const float*)d_in[7];
    const float* b2  = (const float*)d_in[8];
    const float* g2  = (const float*)d_in[9];
    const float* be2 = (const float*)d_in[10];
    const float* m2  = (const float*)d_in[11];
    const float* v2  = (const float*)d_in[12];
    const float* W3  = (const float*)d_in[13];
    const float* b3  = (const float*)d_in[14];
    const float* gw  = (const float*)d_in[15];
    const float* gb  = (const float*)d_in[16];
    float* out = (float*)d_out;

    cudaFuncSetAttribute(moe_main, cudaFuncAttributeMaxDynamicSharedMemorySize, SMEMSZ);

    gap_kernel<<<B_*C_, 256>>>(x);

    prep_kernel<<<(E_*HID_*HID_ + 255) / 256, 256>>>(
        W1, b1, g1, be1, m1, v1, W2, b2, g2, be2, m2, v2, W3);

    const int N = B_ * C_ * HW_;
    int has_aux = (out_size > N) ? 1 : 0;
    gate_kernel<<<1, 32>>>(gw, gb, out + N, has_aux);

    dim3 grid(HW_ / TP, B_);
    moe_main<<<grid, 256, SMEMSZ>>>(x, b3, out);
}

// round 17
// speedup vs baseline: 5.8400x; 1.1106x over previous
#include <cuda_runtime.h>
#include <cuda_bf16.h>
#include <math.h>
#include <stdint.h>

#define E_    4
#define C_    64
#define HID_  128
#define B_    16
#define HW_   16384      // 128*128
#define TP    128        // pixels per tile
#define NT_   512        // threads per block
#define BN_EPS_ 1e-5f

// image pitches (bytes). 144 = 9*16, 272 = 17*16 -> LDSM bank-conflict-free, 16B rows
#define P64   144
#define P128  272
#define W1IMG 18432      // 128 rows * 144
#define W2IMG 34816      // 128 rows * 272
#define W3IMG 17408      // 64  rows * 272

// smem layout (bytes)
#define SM_X   0
#define XIMG   18432     // 128 pixels * 144 (K=64)
#define SM_H   36864
#define HIMG   34816     // 128 pixels * 272 (K=128)
#define SM_W   106496
#define WREG   106496    // weight ring region size
#define SMEMSZ (SM_W + WREG)   // 212992

// weight slot offsets inside W region (verified overlap-free schedule)
#define OF1a 0
#define OF2a 36864
#define OF3a 0
#define OF1b 69632
#define OF2b 0
#define OF3b 69632

// ================= device scratch (no allocs allowed) =================
__device__ uint4 g_w1[E_][2*W1IMG/16];   // [hi img][lo img], rows=o(128), k=c(64)
__device__ uint4 g_w2[E_][2*W2IMG/16];   // rows=o(128), k=i(128)
__device__ uint4 g_w3[E_][2*W3IMG/16];   // rows=c(64),  k=i(128)
__device__ float g_t1 [E_*HID_];
__device__ float g_t2 [E_*HID_];
__device__ float g_gap[B_*C_];
__device__ int   g_sel [B_*2];
__device__ float g_selw[B_*2];

// ================= PTX primitives (baseline ISA, compute_103-safe) =================
__device__ __forceinline__ uint32_t smem_u32(const void* p) {
    uint32_t a;
    asm("{ .reg .u64 t; cvta.to.shared.u64 t, %1; cvt.u32.u64 %0, t; }" : "=r"(a) : "l"(p));
    return a;
}
__device__ __forceinline__ void ldsm_x4(uint32_t* r, uint32_t addr) {
    asm volatile("ldmatrix.sync.aligned.m8n8.x4.shared.b16 {%0,%1,%2,%3}, [%4];"
        : "=r"(r[0]), "=r"(r[1]), "=r"(r[2]), "=r"(r[3]) : "r"(addr));
}
__device__ __forceinline__ void mma16816(float* d, const uint32_t* a, const uint32_t* b) {
    asm volatile("mma.sync.aligned.m16n8k16.row.col.f32.bf16.bf16.f32 "
        "{%0,%1,%2,%3}, {%4,%5,%6,%7}, {%8,%9}, {%0,%1,%2,%3};"
        : "+f"(d[0]), "+f"(d[1]), "+f"(d[2]), "+f"(d[3])
        : "r"(a[0]), "r"(a[1]), "r"(a[2]), "r"(a[3]), "r"(b[0]), "r"(b[1]));
}
__device__ __forceinline__ uint32_t pack_bf2(__nv_bfloat16 a, __nv_bfloat16 b) {
    return (uint32_t)__bfloat16_as_ushort(a) | ((uint32_t)__bfloat16_as_ushort(b) << 16);
}
__device__ __forceinline__ void cp_async16(uint32_t dst, const void* src) {
    asm volatile("cp.async.cg.shared.global [%0], [%1], 16;" :: "r"(dst), "l"(src));
}
#define CP_COMMIT() asm volatile("cp.async.commit_group;" ::: "memory")
#define CP_WAIT(N)  asm volatile("cp.async.wait_group %0;" :: "n"(N) : "memory")

// stage a weight image (n16 uint4 elements) via cp.async; all threads participate
__device__ __forceinline__ void stage_w(uint32_t dst, const uint4* __restrict__ src,
                                        int n16, int tid) {
    for (int i = tid; i < n16; i += NT_) cp_async16(dst + i*16, src + i);
    CP_COMMIT();
}

// ================= kernel 1: global average pool =================
__global__ void gap_kernel(const float* __restrict__ x) {
    int bc = blockIdx.x;
    const float4* p = (const float4*)(x + (size_t)bc * HW_);
    float s = 0.f;
    for (int i = threadIdx.x; i < HW_/4; i += 256) {
        float4 v = p[i];
        s += v.x + v.y + v.z + v.w;
    }
    __shared__ float red[256];
    red[threadIdx.x] = s;
    __syncthreads();
    for (int off = 128; off > 0; off >>= 1) {
        if (threadIdx.x < off) red[threadIdx.x] += red[threadIdx.x + off];
        __syncthreads();
    }
    if (threadIdx.x == 0) g_gap[bc] = red[0] * (1.f / HW_);
}

// ================= kernel 2: gate =================
__global__ void gate_kernel(const float* __restrict__ gw, const float* __restrict__ gb,
                            float* __restrict__ aux_out, int has_aux) {
    __shared__ int   sel_s[B_][2];
    __shared__ float w_s[B_][2];
    int lane = threadIdx.x;
    if (lane < B_) {
        float l[E_];
        #pragma unroll
        for (int e = 0; e < E_; e++) {
            float s = gb[e];
            for (int c = 0; c < C_; c++) s += g_gap[lane*C_ + c] * gw[e*C_ + c];
            l[e] = s;
        }
        float m = l[0];
        #pragma unroll
        for (int e = 1; e < E_; e++) m = fmaxf(m, l[e]);
        float p[E_], sum = 0.f;
        #pragma unroll
        for (int e = 0; e < E_; e++) { p[e] = expf(l[e] - m); sum += p[e]; }
        #pragma unroll
        for (int e = 0; e < E_; e++) p[e] /= sum;
        int i1 = 0;
        #pragma unroll
        for (int e = 1; e < E_; e++) if (p[e] > p[i1]) i1 = e;
        int i2 = -1;
        #pragma unroll
        for (int e = 0; e < E_; e++) {
            if (e == i1) continue;
            if (i2 < 0 || p[e] > p[i2]) i2 = e;
        }
        float denom = p[i1] + p[i2] + 1e-8f;
        float w1 = p[i1] / denom, w2 = p[i2] / denom;
        g_sel[lane*2]  = i1;  g_sel[lane*2+1]  = i2;
        g_selw[lane*2] = w1;  g_selw[lane*2+1] = w2;
        sel_s[lane][0] = i1;  sel_s[lane][1] = i2;
        w_s[lane][0] = w1;    w_s[lane][1] = w2;
    }
    __syncthreads();
    if (lane == 0 && has_aux) {
        float usage[E_] = {0.f, 0.f, 0.f, 0.f};
        for (int b = 0; b < B_; b++) {
            usage[sel_s[b][0]] += w_s[b][0];
            usage[sel_s[b][1]] += w_s[b][1];
        }
        float mean = 0.f;
        #pragma unroll
        for (int e = 0; e < E_; e++) mean += usage[e];
        mean *= 0.25f;
        float var = 0.f;
        #pragma unroll
        for (int e = 0; e < E_; e++) { float d = usage[e] - mean; var += d * d; }
        var *= 0.25f;
        aux_out[0] = var / (mean * mean + 1e-10f);
    }
}

// ================= kernel 3: weight prep (BN fold + bf16 hi/lo padded images) =========
__device__ __forceinline__ void split_st(unsigned char* img, int off, int lo_off, float v) {
    __nv_bfloat16 h = __float2bfloat16(v);
    __nv_bfloat16 l = __float2bfloat16(v - __bfloat162float(h));
    *(__nv_bfloat16*)(img + off)          = h;
    *(__nv_bfloat16*)(img + lo_off + off) = l;
}

__global__ void prep_kernel(const float* __restrict__ W1, const float* __restrict__ b1,
                            const float* __restrict__ g1, const float* __restrict__ be1,
                            const float* __restrict__ m1, const float* __restrict__ v1,
                            const float* __restrict__ W2, const float* __restrict__ b2,
                            const float* __restrict__ g2, const float* __restrict__ be2,
                            const float* __restrict__ m2, const float* __restrict__ v2,
                            const float* __restrict__ W3) {
    int idx = blockIdx.x * 256 + threadIdx.x;     // >= 65536 threads
    if (idx < E_*HID_*HID_) {                     // W2 [e][o][i]
        int e = idx >> 14, r = idx & 16383, o = r >> 7, k = r & 127;
        float inv = g2[e*HID_+o] * rsqrtf(v2[e*HID_+o] + BN_EPS_);
        split_st((unsigned char*)g_w2[e], o*P128 + k*2, W2IMG, W2[idx] * inv);
    }
    if (idx < E_*HID_*C_) {                       // W1 [e][o][c]
        int e = idx >> 13, r = idx & 8191, o = r >> 6, k = r & 63;
        float inv = g1[e*HID_+o] * rsqrtf(v1[e*HID_+o] + BN_EPS_);
        split_st((unsigned char*)g_w1[e], o*P64 + k*2, W1IMG, W1[idx] * inv);
    }
    if (idx < E_*C_*HID_) {                       // W3 [e][c][i]
        int e = idx >> 13, r = idx & 8191, c = r >> 7, k = r & 127;
        split_st((unsigned char*)g_w3[e], c*P128 + k*2, W3IMG, W3[idx]);
    }
    if (idx < E_*HID_) {
        float inv1 = g1[idx] * rsqrtf(v1[idx] + BN_EPS_);
        g_t1[idx] = (b1[idx] - m1[idx]) * inv1 + be1[idx];
        float inv2 = g2[idx] * rsqrtf(v2[idx] + BN_EPS_);
        g_t2[idx] = (b2[idx] - m2[idx]) * inv2 + be2[idx];
    }
}

// ================= warp GEMM: 3-term bf16 error-compensated =================
// A image [row=pixel][k] pitch ap; B image [row=ch][k] pitch bp; both [row][k] ->
// NON-trans ldmatrix for both operands (validated in R15).
template<int MT, int KCH, int NTF>
__device__ __forceinline__ void warp_gemm(uint32_t aHi, uint32_t aLo, int ap,
                                          uint32_t bHi, uint32_t bLo, int bp,
                                          float (&acc)[MT][NTF][4], int lane) {
    uint32_t aoff = (uint32_t)((lane & 15) * ap + (lane >> 4) * 16);
    uint32_t boff = (uint32_t)(((lane & 7) + ((lane >> 4) & 1) * 8) * bp + ((lane >> 3) & 1) * 16);
    #pragma unroll 1
    for (int t = 0; t < 3; t++) {
        uint32_t Ab = ((t == 2) ? aLo : aHi) + aoff;
        uint32_t Bb = ((t == 1) ? bLo : bHi) + boff;
        #pragma unroll
        for (int kc = 0; kc < KCH; kc++) {
            uint32_t a0[4], a1[4];
            ldsm_x4(a0, Ab + kc*32);
            if (MT == 2) ldsm_x4(a1, Ab + 16*ap + kc*32);
            #pragma unroll
            for (int np = 0; np < NTF/2; np++) {
                uint32_t bf[4];
                ldsm_x4(bf, Bb + np*16*bp + kc*32);     // non-trans: [n][k] rows
                mma16816(acc[0][2*np],     a0, bf);
                mma16816(acc[0][2*np + 1], a0, bf + 2);
                if (MT == 2) {
                    mma16816(acc[1][2*np],     a1, bf);
                    mma16816(acc[1][2*np + 1], a1, bf + 2);
                }
            }
        }
    }
}

// Epilogue (layers 1/2): bias + relu + hi/lo bf16 split -> H image (M32 x N32 warp tile)
__device__ __forceinline__ void epi_layer(const float (&acc)[2][4][4], char* smc,
                                          const float* __restrict__ bias,
                                          int pbase, int nbase, int lane) {
    int r = lane >> 2, c2 = (lane & 3) * 2;
    #pragma unroll
    for (int mt = 0; mt < 2; mt++) {
        #pragma unroll
        for (int nt = 0; nt < 4; nt++) {
            int ch = nbase + nt*8 + c2;
            float2 bv = __ldg((const float2*)(bias + ch));
            #pragma unroll
            for (int h = 0; h < 2; h++) {
                int pix = pbase + mt*16 + r + h*8;
                float v0 = fmaxf(acc[mt][nt][2*h]     + bv.x, 0.f);
                float v1 = fmaxf(acc[mt][nt][2*h + 1] + bv.y, 0.f);
                __nv_bfloat16 h0 = __float2bfloat16(v0), h1 = __float2bfloat16(v1);
                __nv_bfloat16 l0 = __float2bfloat16(v0 - __bfloat162float(h0));
                __nv_bfloat16 l1 = __float2bfloat16(v1 - __bfloat162float(h1));
                int off = pix*P128 + ch*2;
                *(uint32_t*)(smc + SM_H + off)        = pack_bf2(h0, h1);
                *(uint32_t*)(smc + SM_H + HIMG + off) = pack_bf2(l0, l1);
            }
        }
    }
}

// full layer 1 or 2: gemm into fresh acc (caller handles syncs around it)
template<int KCH, int PITCH>
__device__ __forceinline__ void do_layer12(uint32_t aBase, uint32_t aImgSz, int ap,
                                           uint32_t wBase, uint32_t wImgSz,
                                           char* smc, const float* bias,
                                           int pbase, int nbase, int lane,
                                           bool sync_before_epi) {
    float acc[2][4][4];
    #pragma unroll
    for (int mt = 0; mt < 2; mt++)
        #pragma unroll
        for (int nt = 0; nt < 4; nt++)
            #pragma unroll
            for (int j = 0; j < 4; j++) acc[mt][nt][j] = 0.f;
    warp_gemm<2, KCH, 4>(aBase + pbase*ap, aBase + aImgSz + pbase*ap, ap,
                         wBase + nbase*PITCH, wBase + wImgSz + nbase*PITCH, PITCH,
                         acc, lane);
    if (sync_before_epi) __syncthreads();   // L2: all H reads done before overwrite
    epi_layer(acc, smc, bias, pbase, nbase, lane);
}

// ================= main fused kernel =================
__global__ void __launch_bounds__(NT_, 1)
moe_main(const float* __restrict__ x, const float* __restrict__ b3,
         float* __restrict__ out) {
    extern __shared__ __align__(16) char smc[];
    const uint32_t smb = smem_u32(smc);
    const int tid  = threadIdx.x;
    const int wid  = tid >> 5;
    const int lane = tid & 31;
    const int wm   = wid & 3;           // L1/L2: M block (32 pixels)
    const int wn   = wid >> 2;          // L1/L2: N block (32 ch), 0..3
    const int pbase  = wm * 32;
    const int wm3  = wid & 7;           // L3: M block (16 pixels)
    const int wn3  = wid >> 3;          // L3: N block (32 ch), 0..1
    const int pbase3 = wm3 * 16;
    const int b    = blockIdx.y;
    const int p0   = blockIdx.x * TP;
    const int r    = lane >> 2, c2 = (lane & 3) * 2;

    const int   e0  = g_sel[b*2],     e1  = g_sel[b*2 + 1];
    const float gw0 = g_selw[b*2],    gw1 = g_selw[b*2 + 1];

    // kick W1(e0) + W2(e0) prefetch immediately (g0, g1)
    stage_w(smb + SM_W + OF1a, g_w1[e0], 2*W1IMG/16, tid);
    stage_w(smb + SM_W + OF2a, g_w2[e0], 2*W2IMG/16, tid);

    // ---- stage X as A image: [pixel][c] bf16 hi/lo, pitch 144 ----
    for (int it = tid; it < 1024; it += NT_) {
        int p  = it & 127;
        int cg = it >> 7;              // 8 channels per item
        const float* xp = x + (size_t)b * C_ * HW_ + (size_t)(cg * 8) * HW_ + p0 + p;
        uint32_t hw[4], lw[4];
        #pragma unroll
        for (int q = 0; q < 4; q++) {
            float v0 = __ldg(xp + (size_t)(q*2)     * HW_);
            float v1 = __ldg(xp + (size_t)(q*2 + 1) * HW_);
            __nv_bfloat16 h0 = __float2bfloat16(v0), h1 = __float2bfloat16(v1);
            __nv_bfloat16 l0 = __float2bfloat16(v0 - __bfloat162float(h0));
            __nv_bfloat16 l1 = __float2bfloat16(v1 - __bfloat162float(h1));
            hw[q] = pack_bf2(h0, h1);
            lw[q] = pack_bf2(l0, l1);
        }
        int off = p * P64 + cg * 16;
        *(uint4*)(smc + SM_X + off)        = make_uint4(hw[0], hw[1], hw[2], hw[3]);
        *(uint4*)(smc + SM_X + XIMG + off) = make_uint4(lw[0], lw[1], lw[2], lw[3]);
    }

    float oacc[4][4];
    #pragma unroll
    for (int nt = 0; nt < 4; nt++)
        #pragma unroll
        for (int j = 0; j < 4; j++) oacc[nt][j] = 0.f;

    // ============ expert 0 ============
    CP_WAIT(1); __syncthreads();                          // W1(e0) + X visible
    do_layer12<4, P64>(smb + SM_X, XIMG, P64, smb + SM_W + OF1a, W1IMG,
                       smc, g_t1 + e0*HID_, pbase, wn*32, lane, false);
    CP_WAIT(0); __syncthreads();                          // W2 visible; H visible; W1 reads done
    stage_w(smb + SM_W + OF3a, g_w3[e0], 2*W3IMG/16, tid);            // g2

    {   // layer 2 (sync inside before epi; issue W1(e1) between gemm-sync and epi)
        float acc[2][4][4];
        #pragma unroll
        for (int mt = 0; mt < 2; mt++)
            #pragma unroll
            for (int nt = 0; nt < 4; nt++)
                #pragma unroll
                for (int j = 0; j < 4; j++) acc[mt][nt][j] = 0.f;
        warp_gemm<2, 8, 4>(smb + SM_H + pbase*P128, smb + SM_H + HIMG + pbase*P128, P128,
                           smb + SM_W + OF2a + (wn*32)*P128, smb + SM_W + OF2a + W2IMG + (wn*32)*P128, P128,
                           acc, lane);
        __syncthreads();                                  // all H + W2 reads done
        stage_w(smb + SM_W + OF1b, g_w1[e1], 2*W1IMG/16, tid);        // g3
        epi_layer(acc, smc, g_t2 + e0*HID_, pbase, wn*32, lane);
    }
    CP_WAIT(1); __syncthreads();                          // W3(e0) visible; H' visible
    {   // layer 3: accumulate
        float acc[1][4][4];
        #pragma unroll
        for (int nt = 0; nt < 4; nt++)
            #pragma unroll
            for (int j = 0; j < 4; j++) acc[0][nt][j] = 0.f;
        warp_gemm<1, 8, 4>(smb + SM_H + pbase3*P128, smb + SM_H + HIMG + pbase3*P128, P128,
                           smb + SM_W + OF3a + (wn3*32)*P128, smb + SM_W + OF3a + W3IMG + (wn3*32)*P128, P128,
                           acc, lane);
        const float* bp = b3 + e0 * C_;
        #pragma unroll
        for (int nt = 0; nt < 4; nt++) {
            int ch = wn3*32 + nt*8 + c2;
            float2 bv = __ldg((const float2*)(bp + ch));
            oacc[nt][0] = fmaf(gw0, acc[0][nt][0] + bv.x, oacc[nt][0]);
            oacc[nt][1] = fmaf(gw0, acc[0][nt][1] + bv.y, oacc[nt][1]);
            oacc[nt][2] = fmaf(gw0, acc[0][nt][2] + bv.x, oacc[nt][2]);
            oacc[nt][3] = fmaf(gw0, acc[0][nt][3] + bv.y, oacc[nt][3]);
        }
    }
    __syncthreads();                                      // W3 + H reads done
    stage_w(smb + SM_W + OF2b, g_w2[e1], 2*W2IMG/16, tid);            // g4

    // ============ expert 1 ============
    CP_WAIT(1); __syncthreads();                          // W1(e1) visible
    do_layer12<4, P64>(smb + SM_X, XIMG, P64, smb + SM_W + OF1b, W1IMG,
                       smc, g_t1 + e1*HID_, pbase, wn*32, lane, false);
    CP_WAIT(0); __syncthreads();                          // W2(e1) visible; H visible; W1 reads done
    stage_w(smb + SM_W + OF3b, g_w3[e1], 2*W3IMG/16, tid);            // g5

    {   // layer 2
        float acc[2][4][4];
        #pragma unroll
        for (int mt = 0; mt < 2; mt++)
            #pragma unroll
            for (int nt = 0; nt < 4; nt++)
                #pragma unroll
                for (int j = 0; j < 4; j++) acc[mt][nt][j] = 0.f;
        warp_gemm<2, 8, 4>(smb + SM_H + pbase*P128, smb + SM_H + HIMG + pbase*P128, P128,
                           smb + SM_W + OF2b + (wn*32)*P128, smb + SM_W + OF2b + W2IMG + (wn*32)*P128, P128,
                           acc, lane);
        __syncthreads();                                  // all H reads done
        epi_layer(acc, smc, g_t2 + e1*HID_, pbase, wn*32, lane);
    }
    CP_WAIT(0); __syncthreads();                          // W3(e1) visible; H' visible
    {   // layer 3: accumulate
        float acc[1][4][4];
        #pragma unroll
        for (int nt = 0; nt < 4; nt++)
            #pragma unroll
            for (int j = 0; j < 4; j++) acc[0][nt][j] = 0.f;
        warp_gemm<1, 8, 4>(smb + SM_H + pbase3*P128, smb + SM_H + HIMG + pbase3*P128, P128,
                           smb + SM_W + OF3b + (wn3*32)*P128, smb + SM_W + OF3b + W3IMG + (wn3*32)*P128, P128,
                           acc, lane);
        const float* bp = b3 + e1 * C_;
        #pragma unroll
        for (int nt = 0; nt < 4; nt++) {
            int ch = wn3*32 + nt*8 + c2;
            float2 bv = __ldg((const float2*)(bp + ch));
            oacc[nt][0] = fmaf(gw1, acc[0][nt][0] + bv.x, oacc[nt][0]);
            oacc[nt][1] = fmaf(gw1, acc[0][nt][1] + bv.y, oacc[nt][1]);
            oacc[nt][2] = fmaf(gw1, acc[0][nt][2] + bv.x, oacc[nt][2]);
            oacc[nt][3] = fmaf(gw1, acc[0][nt][3] + bv.y, oacc[nt][3]);
        }
    }

    // ---- store: out[b][ch][p0 + pixel], warp tile M16 x N32 ----
    float* ob = out + (size_t)b * C_ * HW_ + p0;
    #pragma unroll
    for (int nt = 0; nt < 4; nt++) {
        int ch = wn3*32 + nt*8 + c2;
        #pragma unroll
        for (int h = 0; h < 2; h++) {
            int pix = pbase3 + r + h*8;
            ob[(size_t)ch * HW_ + pix]       = oacc[nt][2*h];
            ob[(size_t)(ch + 1) * HW_ + pix] = oacc[nt][2*h + 1];
        }
    }
}

// ================= launch =================
extern "C" void kernel_launch(void* const* d_in, const int* in_sizes, int n_in,
                              void* d_out, int out_size) {
    const float* x   = (const float*)d_in[0];
    const float* W1  = (const float*)d_in[1];
    const float* b1  = (const float*)d_in[2];
    const float* g1  = (const float*)d_in[3];
    const float* be1 = (const float*)d_in[4];
    const float* m1  = (const float*)d_in[5];
    const float* v1  = (const float*)d_in[6];
    const float* W2  = (const float*)d_in[7];
    const float* b2  = (const float*)d_in[8];
    const float* g2  = (const float*)d_in[9];
    const float* be2 = (const float*)d_in[10];
    const float* m2  = (const float*)d_in[11];
    const float* v2  = (const float*)d_in[12];
    const float* W3  = (const float*)d_in[13];
    const float* b3  = (const float*)d_in[14];
    const float* gw  = (const float*)d_in[15];
    const float* gb  = (const float*)d_in[16];
    float* out = (float*)d_out;

    cudaFuncSetAttribute(moe_main, cudaFuncAttributeMaxDynamicSharedMemorySize, SMEMSZ);

    gap_kernel<<<B_*C_, 256>>>(x);

    prep_kernel<<<(E_*HID_*HID_ + 255) / 256, 256>>>(
        W1, b1, g1, be1, m1, v1, W2, b2, g2, be2, m2, v2, W3);

    const int N = B_ * C_ * HW_;
    int has_aux = (out_size > N) ? 1 : 0;
    gate_kernel<<<1, 32>>>(gw, gb, out + N, has_aux);

    dim3 grid(HW_ / TP, B_);
    moe_main<<<grid, NT_, SMEMSZ>>>(x, b3, out);
}